// round 8
// baseline (speedup 1.0000x reference)
#include <cuda_runtime.h>

#define IMG     512
#define WSTRIP  128
#define HSEG    128
#define HALO    5
#define SROW    138
#define NSTREAM (11 * SROW)

typedef unsigned long long u64;

static __device__ __forceinline__ u64 pk(float lo, float hi) {
    u64 r; asm("mov.b64 %0, {%1, %2};" : "=l"(r) : "f"(lo), "f"(hi)); return r;
}
static __device__ __forceinline__ void upk(u64 v, float& lo, float& hi) {
    asm("mov.b64 {%0, %1}, %2;" : "=f"(lo), "=f"(hi) : "l"(v));
}
static __device__ __forceinline__ u64 fma2(u64 a, u64 b, u64 c) {
    u64 d; asm("fma.rn.f32x2 %0, %1, %2, %3;" : "=l"(d) : "l"(a), "l"(b), "l"(c)); return d;
}
static __device__ __forceinline__ u64 mul2(u64 a, u64 b) {
    u64 d; asm("mul.rn.f32x2 %0, %1, %2;" : "=l"(d) : "l"(a), "l"(b)); return d;
}

#define SAB(B, P, C) sABb[((B) * 11 + (P)) * SROW + (C)]
#define SFQ(B, P, C) sFQb[((B) * 11 + (P)) * SROW + (C)]

// Group-dispatched row load into a stage set.
//   X (grp==0): SA=a, SB=b at c0;  SC=a, SD=b at c1 (tail)
//   Y (grp==1): SA=f at c0;        SC=f at c1 (tail)
#define LOADST(SA, SB, SC, SD, R) do {                                        \
    const int _r = (R);                                                       \
    SA = 0.f; SB = 0.f; SC = 0.f; SD = 0.f;                                   \
    if (_r >= ract_lo && _r <= ract_hi) {                                     \
        if (grp == 0) {                                                       \
            if (c0v) { const int _i = _r * IMG + c0; SA = ga[_i]; SB = gb[_i]; } \
            if (c1v) { const int _i = _r * IMG + c1; SC = ga[_i]; SD = gb[_i]; } \
        } else {                                                              \
            if (c0v) { const int _i = _r * IMG + c0; SA = gf[_i]; }           \
            if (c1v) { const int _i = _r * IMG + c1; SC = gf[_i]; }           \
        }                                                                     \
    }                                                                         \
} while (0)

// Group-dispatched packed store of a stage set into buffer NB, slot P.
#define STST(SA, SB, SC, SD, NB, P) do {                                      \
    if (grp == 0) {                                                           \
        SAB(NB, P, col) = pk(SA, SB);                                         \
        if (col < 10) SAB(NB, P, col + 128) = pk(SC, SD);                     \
    } else {                                                                  \
        SFQ(NB, P, col) = pk(SA, (SA) * (SA));                                \
        if (col < 10) SFQ(NB, P, col + 128) = pk(SC, (SC) * (SC));            \
    }                                                                         \
} while (0)

__global__ void __launch_bounds__(256, 2)
ssim_fused_kernel(const float* __restrict__ A, const float* __restrict__ B,
                  const float* __restrict__ F, float* __restrict__ out,
                  float scale)
{
    constexpr float W[11] = {0.00102838f, 0.00759876f, 0.03600077f, 0.10936069f,
                             0.21300553f, 0.26601172f, 0.21300553f, 0.10936069f,
                             0.03600077f, 0.00759876f, 0.00102838f};
    constexpr float C1 = 0.0001f, C2 = 0.0009f;

    extern __shared__ u64 dsm[];
    u64* sABb  = dsm;                       // [2][11][SROW] packed (a, b)
    u64* sFQb  = dsm + 2 * NSTREAM;         // [2][11][SROW] packed (f, f*f)
    u64* epi   = dsm + 4 * NSTREAM;         // [2 slots][2 vals][128 cols]
    float* wpart = (float*)(epi + 512);

    const int t   = threadIdx.x;
    const int grp = t >> 7;                 // 0: channels (a,b),(a2,b2); 1: (f,f2),(af,bf)
    const int col = t & 127;
    const int x0 = blockIdx.x * WSTRIP;
    const int y0 = blockIdx.y * HSEG;
    const int y1 = y0 + HSEG;
    const size_t poff = (size_t)blockIdx.z * (size_t)(IMG * IMG);
    const float* ga = A + poff;
    const float* gb = B + poff;
    const float* gf = F + poff;

    u64 W2[6];
#pragma unroll
    for (int j = 0; j < 6; ++j) W2[j] = pk(W[j], W[j]);

    // per-thread vertical ring: 2 packed channels x 11 pending output rows
    // X: r0 = (Sa,Sb), r1 = (Sa2,Sb2)    Y: r0 = (Sf,Sf2), r1 = (Saf,Sbf)
    u64 r0[11], r1[11];
#pragma unroll
    for (int s = 0; s < 11; ++s) { r0[s] = 0; r1[s] = 0; }

    float ssum = 0.0f;

    const int ract_lo = (y0 - HALO) < 0 ? 0 : (y0 - HALO);
    const int ract_hi = (y1 + HALO - 1) > (IMG - 1) ? (IMG - 1) : (y1 + HALO - 1);

    const int  c0  = x0 - HALO + col;
    const bool c0v = (c0 >= 0) && (c0 < IMG);
    const int  c1  = c0 + 128;
    const bool c1v = (col < 10) && (c1 < IMG);

    const int base    = ((y0 - HALO + 11) / 11) * 11 - 11;   // multiple of 11 <= y0-5
    const int nchunks = (y1 + HALO - base + 10) / 11;

    // ---- prologue: stage rows base..base+10 into buffer 0 ----
#pragma unroll
    for (int p = 0; p < 11; ++p) {
        float ta, tb, tc, td;
        LOADST(ta, tb, tc, td, base + p);
        STST(ta, tb, tc, td, 0, p);
    }
    // stage sets: set0 holds row base+11 (STS'd at phase 0), set1 holds base+12
    float s0a, s0b, s0c, s0d;
    float s1a, s1b, s1c, s1d;
    LOADST(s0a, s0b, s0c, s0d, base + 11);
    LOADST(s1a, s1b, s1c, s1d, base + 12);
    __syncthreads();

#pragma unroll 1
    for (int chk = 0; chk < nchunks; ++chk) {
        const int rbase = base + chk * 11;
        const int bb = chk & 1, nb = bb ^ 1;
#pragma unroll
        for (int p = 0; p < 11; ++p) {
            const int row = rbase + p;

            // 1) STS row loaded 2 phases ago; refill with row rbase+13+p
            if ((p & 1) == 0) {
                STST(s0a, s0b, s0c, s0d, nb, p);
                LOADST(s0a, s0b, s0c, s0d, rbase + 13 + p);
            } else {
                STST(s1a, s1b, s1c, s1d, nb, p);
                LOADST(s1a, s1b, s1c, s1d, rbase + 13 + p);
            }

            // 2) horizontal conv (group-specific) + vertical scatter (shared)
            if (row >= ract_lo && row <= ract_hi) {
                u64 h0 = 0, h1 = 0;
                if (grp == 0) {
                    const u64* rab = &SAB(bb, p, col);
#pragma unroll
                    for (int j = 0; j < 11; ++j) {
                        const u64 w2  = W2[j < 6 ? j : 10 - j];
                        const u64 vab = rab[j];
                        h0 = fma2(vab, w2, h0);            // (Sa, Sb)
                        const u64 t1 = mul2(vab, w2);
                        h1 = fma2(t1, vab, h1);            // (Sa2, Sb2)
                    }
                } else {
                    const u64* rab = &SAB(bb, p, col);
                    const u64* rfq = &SFQ(bb, p, col);
#pragma unroll
                    for (int j = 0; j < 11; ++j) {
                        const u64 w2  = W2[j < 6 ? j : 10 - j];
                        const u64 vfq = rfq[j];
                        const u64 vab = rab[j];
                        h0 = fma2(vfq, w2, h0);            // (Sf, Sf2)
                        const u64 t1 = mul2(vab, w2);
                        float fl, fh; upk(vfq, fl, fh);
                        h1 = fma2(t1, pk(fl, fl), h1);     // (Saf, Sbf)
                    }
                }
#pragma unroll
                for (int j = 0; j < 11; ++j) {
                    const int s  = (p + 6 + j) % 11;
                    const u64 w2 = W2[j < 6 ? j : 10 - j];
                    r0[s] = fma2(h0, w2, r0[s]);
                    r1[s] = fma2(h1, w2, r1[s]);
                }
            }

            // 3) output row o = row-5 completes in slot sd
            const int  o    = row - HALO;
            const int  sd   = (p + 6) % 11;
            const bool oval = (o >= y0) && (o < y1);

            // Y publishes its 2 ring values for this row (double-slotted by o&1)
            if (grp == 1 && oval) {
                epi[(o & 1) * 256 + col]       = r0[sd];   // (muF, EF2)
                epi[(o & 1) * 256 + 128 + col] = r1[sd];   // (EAF, EBF)
            }

            __syncthreads();

            // X consumes and computes both SSIM pairs
            if (grp == 0 && oval) {
                float muA, muB; upk(r0[sd], muA, muB);
                float EA2, EB2; upk(r1[sd], EA2, EB2);
                float muF, EF2; upk(epi[(o & 1) * 256 + col], muF, EF2);
                float EAF, EBF; upk(epi[(o & 1) * 256 + 128 + col], EAF, EBF);
                const float muF2 = muF * muF;
                const float mc   = muF2 + C1;              // mu2^2 + C1 (shared)
                const float s2   = (EF2 - muF2) + C2;      // sigma2 + C2 (shared)
                float nA, dA, nB, dB;
                {
                    const float m12 = muA * muF;
                    const float mus = muA * muA;
                    nA = fmaf(2.0f, m12, C1) * fmaf(2.0f, EAF - m12, C2);
                    dA = (mus + mc) * ((EA2 - mus) + s2);
                }
                {
                    const float m12 = muB * muF;
                    const float mus = muB * muB;
                    nB = fmaf(2.0f, m12, C1) * fmaf(2.0f, EBF - m12, C2);
                    dB = (mus + mc) * ((EB2 - mus) + s2);
                }
                // one MUFU: ssimA + ssimB = (nA*dB + nB*dA) / (dA*dB)
                ssum += __fdividef(fmaf(nA, dB, nB * dA), dA * dB);
            }
            r0[sd] = 0; r1[sd] = 0;
        }
        // 11 (odd) phases per chunk -> swap stage sets to keep parity static
        { float x;
          x = s0a; s0a = s1a; s1a = x;
          x = s0b; s0b = s1b; s1b = x;
          x = s0c; s0c = s1c; s1c = x;
          x = s0d; s0d = s1d; s1d = x; }
    }

    // block reduction -> single atomic per block (Y threads contribute 0)
    const unsigned lane = t & 31u;
    const unsigned wid  = (unsigned)t >> 5;
#pragma unroll
    for (int off = 16; off; off >>= 1)
        ssum += __shfl_down_sync(0xffffffffu, ssum, off);
    if (lane == 0) wpart[wid] = ssum;
    __syncthreads();
    if (t == 0) {
        float v = 0.f;
#pragma unroll
        for (int w = 0; w < 8; ++w) v += wpart[w];
        atomicAdd(out, v * scale);
    }
}

__global__ void zero_kernel(float* out) { *out = 0.0f; }

#define SMEM_BYTES (4 * NSTREAM * 8 + 512 * 8 + 64)

extern "C" void kernel_launch(void* const* d_in, const int* in_sizes, int n_in,
                              void* d_out, int out_size)
{
    const float* A = (const float*)d_in[0];
    const float* B = (const float*)d_in[1];
    const float* F = (const float*)d_in[2];
    float* out = (float*)d_out;

    const int nplanes = in_sizes[0] / (IMG * IMG);   // 48
    const float scale = 0.5f / (float)in_sizes[0];

    cudaFuncSetAttribute(ssim_fused_kernel,
                         cudaFuncAttributeMaxDynamicSharedMemorySize, SMEM_BYTES);

    zero_kernel<<<1, 1>>>(out);
    dim3 grid(IMG / WSTRIP, IMG / HSEG, nplanes);
    ssim_fused_kernel<<<grid, 256, SMEM_BYTES>>>(A, B, F, out, scale);
}

// round 9
// speedup vs baseline: 1.5217x; 1.5217x over previous
#include <cuda_runtime.h>

#define IMG     512
#define WSTRIP  128
#define HSEG    128
#define HALO    5
#define SROW    138

typedef unsigned long long u64;

static __device__ __forceinline__ u64 pk(float lo, float hi) {
    u64 r; asm("mov.b64 %0, {%1, %2};" : "=l"(r) : "f"(lo), "f"(hi)); return r;
}
static __device__ __forceinline__ void upk(u64 v, float& lo, float& hi) {
    asm("mov.b64 {%0, %1}, %2;" : "=f"(lo), "=f"(hi) : "l"(v));
}
static __device__ __forceinline__ u64 fma2(u64 a, u64 b, u64 c) {
    u64 d; asm("fma.rn.f32x2 %0, %1, %2, %3;" : "=l"(d) : "l"(a), "l"(b), "l"(c)); return d;
}
static __device__ __forceinline__ u64 mul2(u64 a, u64 b) {
    u64 d; asm("mul.rn.f32x2 %0, %1, %2;" : "=l"(d) : "l"(a), "l"(b)); return d;
}
static __device__ __forceinline__ unsigned s2u(const void* p) {
    return (unsigned)__cvta_generic_to_shared(p);
}
// 128-bit shared load as two b64 (lands directly in fma2-ready register pairs)
static __device__ __forceinline__ void lds2(u64& x, u64& y, unsigned a) {
    asm("ld.shared.v2.b64 {%0, %1}, [%2];" : "=l"(x), "=l"(y) : "r"(a) : "memory");
}
static __device__ __forceinline__ void sts2(unsigned a, u64 x, u64 y) {
    asm volatile("st.shared.v2.b64 [%0], {%1, %2};" :: "r"(a), "l"(x), "l"(y) : "memory");
}

// Load one global row (zero-filled out of bounds) into a register stage set.
#define LOADSTAGE(PA, PB, PF, QA, QB, QF, R) do {                            \
    const int _r = (R);                                                      \
    PA = 0.f; PB = 0.f; PF = 0.f; QA = 0.f; QB = 0.f; QF = 0.f;              \
    if (_r >= ract_lo && _r <= ract_hi) {                                    \
        if (c0v) { const int _i = _r * IMG + c0; PA = ga[_i]; PB = gb[_i]; PF = gf[_i]; } \
        if (c1v) { const int _i = _r * IMG + c1; QA = ga[_i]; QB = gb[_i]; QF = gf[_i]; } \
    }                                                                        \
} while (0)

// Store a staged row into smem buffer NB slot P as one 16B record per column:
//   (a, b | f, f*f)
#define STSTAGE(PA, PB, PF, QA, QB, QF, NB, P) do {                          \
    sts2(s2u(&sQ[NB][P][t][0]), pk(PA, PB), pk(PF, (PF) * (PF)));            \
    if (t < 10)                                                              \
        sts2(s2u(&sQ[NB][P][t + 128][0]), pk(QA, QB), pk(QF, (QF) * (QF)));  \
} while (0)

__global__ void __launch_bounds__(128, 3)
ssim_fused_kernel(const float* __restrict__ A, const float* __restrict__ B,
                  const float* __restrict__ F, float* __restrict__ out,
                  float scale)
{
    constexpr float W[11] = {0.00102838f, 0.00759876f, 0.03600077f, 0.10936069f,
                             0.21300553f, 0.26601172f, 0.21300553f, 0.10936069f,
                             0.03600077f, 0.00759876f, 0.00102838f};
    constexpr float C1 = 0.0001f, C2 = 0.0009f;

    const int t  = threadIdx.x;
    const int x0 = blockIdx.x * WSTRIP;
    const int y0 = blockIdx.y * HSEG;
    const int y1 = y0 + HSEG;
    const size_t poff = (size_t)blockIdx.z * (size_t)(IMG * IMG);
    const float* ga = A + poff;
    const float* gb = B + poff;
    const float* gf = F + poff;

    // double-buffered 11-row chunks; one interleaved 16B record per column
    __shared__ __align__(16) u64 sQ[2][11][SROW][2];
    __shared__ float wpart[4];

    u64 W2[6];
#pragma unroll
    for (int j = 0; j < 6; ++j) W2[j] = pk(W[j], W[j]);

    // vertical ring: 4 packed channels x 11 pending output rows
    u64 aAB[11], aAB2[11], aABF[11], aFF[11];
#pragma unroll
    for (int s = 0; s < 11; ++s) { aAB[s] = 0; aAB2[s] = 0; aABF[s] = 0; aFF[s] = 0; }

    float ssum = 0.0f;

    const int ract_lo = (y0 - HALO) < 0 ? 0 : (y0 - HALO);
    const int ract_hi = (y1 + HALO - 1) > (IMG - 1) ? (IMG - 1) : (y1 + HALO - 1);

    const int  c0  = x0 - HALO + t;
    const bool c0v = (c0 >= 0) && (c0 < IMG);
    const int  c1  = c0 + 128;
    const bool c1v = (t < 10) && (c1 < IMG);

    const int base    = ((y0 - HALO + 11) / 11) * 11 - 11;   // multiple of 11 <= y0-5
    const int nchunks = (y1 + HALO - base + 10) / 11;

    // ---- prologue: stage rows base..base+10 into buffer 0 ----
#pragma unroll
    for (int p = 0; p < 11; ++p) {
        float va, vb, vf, ua, ub, uf;
        LOADSTAGE(va, vb, vf, ua, ub, uf, base + p);
        STSTAGE(va, vb, vf, ua, ub, uf, 0, p);
    }

    // stage sets: S0 holds row base+11 (STS'd at phase 0), S1 holds base+12
    float p0a, p0b, p0f, q0a, q0b, q0f;
    float p1a, p1b, p1f, q1a, q1b, q1f;
    LOADSTAGE(p0a, p0b, p0f, q0a, q0b, q0f, base + 11);
    LOADSTAGE(p1a, p1b, p1f, q1a, q1b, q1f, base + 12);
    __syncthreads();

#pragma unroll 1
    for (int chk = 0; chk < nchunks; ++chk) {
        const int rbase = base + chk * 11;
        const int bb = chk & 1, nb = bb ^ 1;
#pragma unroll
        for (int p = 0; p < 11; ++p) {
            const int row = rbase + p;

            // 1) STS the row loaded 2 phases ago (row rbase+11+p), then
            //    refill the freed stage with row rbase+13+p (2-phase cover).
            if ((p & 1) == 0) {
                STSTAGE(p0a, p0b, p0f, q0a, q0b, q0f, nb, p);
                LOADSTAGE(p0a, p0b, p0f, q0a, q0b, q0f, rbase + 13 + p);
            } else {
                STSTAGE(p1a, p1b, p1f, q1a, q1b, q1f, nb, p);
                LOADSTAGE(p1a, p1b, p1f, q1a, q1b, q1f, rbase + 13 + p);
            }

            // 2) horizontal conv + vertical scatter
            if (row >= ract_lo && row <= ract_hi) {
                const unsigned ad = s2u(&sQ[bb][p][t][0]);
                u64 hAB = 0, hAB2 = 0, hABF = 0, hFF = 0;
#pragma unroll
                for (int j = 0; j < 11; ++j) {
                    const u64 w2 = W2[j < 6 ? j : 10 - j];
                    u64 vab, vfq;
                    lds2(vab, vfq, ad + j * 16u);
                    hAB  = fma2(vab, w2, hAB);         // (Sa, Sb)
                    const u64 t1 = mul2(vab, w2);      // (w a, w b)
                    hAB2 = fma2(t1, vab, hAB2);        // (Sa2, Sb2)
                    hFF  = fma2(vfq, w2, hFF);         // (Sf, Sf2)
                    float fl, fh; upk(vfq, fl, fh);
                    hABF = fma2(t1, pk(fl, fl), hABF); // (Saf, Sbf)
                }
#pragma unroll
                for (int j = 0; j < 11; ++j) {
                    const int s  = (p + 6 + j) % 11;
                    const u64 w2 = W2[j < 6 ? j : 10 - j];
                    aAB [s] = fma2(hAB , w2, aAB [s]);
                    aAB2[s] = fma2(hAB2, w2, aAB2[s]);
                    aABF[s] = fma2(hABF, w2, aABF[s]);
                    aFF [s] = fma2(hFF , w2, aFF [s]);
                }
            }

            // 3) output row o = row - 5 completes in slot (p+6)%11
            {
                const int o  = row - HALO;
                const int sd = (p + 6) % 11;
                if (o >= y0 && o < y1) {
                    float muA, muB, EA2, EB2, EAF, EBF, muF, EF2;
                    upk(aAB [sd], muA, muB);
                    upk(aAB2[sd], EA2, EB2);
                    upk(aABF[sd], EAF, EBF);
                    upk(aFF [sd], muF, EF2);
                    const float muF2 = muF * muF;
                    const float mc   = muF2 + C1;            // mu2^2 + C1 (shared)
                    const float s2   = (EF2 - muF2) + C2;    // sigma2 + C2 (shared)
                    float nA, dA, nB, dB;
                    {
                        const float m12 = muA * muF;
                        const float mus = muA * muA;
                        nA = fmaf(2.0f, m12, C1) * fmaf(2.0f, EAF - m12, C2);
                        dA = (mus + mc) * ((EA2 - mus) + s2);
                    }
                    {
                        const float m12 = muB * muF;
                        const float mus = muB * muB;
                        nB = fmaf(2.0f, m12, C1) * fmaf(2.0f, EBF - m12, C2);
                        dB = (mus + mc) * ((EB2 - mus) + s2);
                    }
                    // one MUFU: ssimA + ssimB = (nA*dB + nB*dA) / (dA*dB)
                    ssum += __fdividef(fmaf(nA, dB, nB * dA), dA * dB);
                }
                aAB[sd] = 0; aAB2[sd] = 0; aABF[sd] = 0; aFF[sd] = 0;
            }
        }
        __syncthreads();
        // 11 (odd) phases per chunk -> swap stage sets to keep parity static
        { float x;
          x = p0a; p0a = p1a; p1a = x;
          x = p0b; p0b = p1b; p1b = x;
          x = p0f; p0f = p1f; p1f = x;
          x = q0a; q0a = q1a; q1a = x;
          x = q0b; q0b = q1b; q1b = x;
          x = q0f; q0f = q1f; q1f = x; }
    }

    // block reduction -> single atomic per block
    const unsigned lane = t & 31u;
    const unsigned wid  = (unsigned)t >> 5;
#pragma unroll
    for (int off = 16; off; off >>= 1)
        ssum += __shfl_down_sync(0xffffffffu, ssum, off);
    if (lane == 0) wpart[wid] = ssum;
    __syncthreads();
    if (t == 0)
        atomicAdd(out, (wpart[0] + wpart[1] + wpart[2] + wpart[3]) * scale);
}

__global__ void zero_kernel(float* out) { *out = 0.0f; }

extern "C" void kernel_launch(void* const* d_in, const int* in_sizes, int n_in,
                              void* d_out, int out_size)
{
    const float* A = (const float*)d_in[0];
    const float* B = (const float*)d_in[1];
    const float* F = (const float*)d_in[2];
    float* out = (float*)d_out;

    const int nplanes = in_sizes[0] / (IMG * IMG);   // 48
    const float scale = 0.5f / (float)in_sizes[0];

    zero_kernel<<<1, 1>>>(out);
    dim3 grid(IMG / WSTRIP, IMG / HSEG, nplanes);
    ssim_fused_kernel<<<grid, 128>>>(A, B, F, out, scale);
}